// round 6
// baseline (speedup 1.0000x reference)
#include <cuda_runtime.h>
#include <cuda_bf16.h>
#include <math.h>

#define D     512
#define KTOP  11          // 1 + K
#define KNEI  9           // reference uses idx[1:K] = 9 neighbors
#define NCLS  100
#define RPB   256         // rows per block in fused kernel (977 blocks)
#define NMAX  250000
#define GMAX  ((NMAX + RPB - 1) / RPB)        // 977
#define NCAND (GMAX * KTOP)                   // 10747
#define MBLK  ((NCAND + 255) / 256)           // 42 merge blocks
#define NC2   (MBLK * KTOP)                   // 462

// Scratch (allocation-free rule: __device__ globals)
__device__ unsigned long long g_cand[NCAND];
__device__ unsigned long long g_cand2[NC2];

// ---- monotonic float key: bigger key == bigger value; tie -> smaller index wins ----
__device__ __forceinline__ unsigned long long make_key(float v, unsigned int idx) {
    unsigned int b = __float_as_uint(v);
    b = (b & 0x80000000u) ? ~b : (b | 0x80000000u);
    return ((unsigned long long)b << 32) | (unsigned int)(~idx);
}
__device__ __forceinline__ float key_val(unsigned long long k) {
    unsigned int o = (unsigned int)(k >> 32);
    unsigned int b = (o & 0x80000000u) ? (o ^ 0x80000000u) : ~o;
    return __uint_as_float(b);
}
__device__ __forceinline__ unsigned int key_idx(unsigned long long k) {
    return ~(unsigned int)(k & 0xFFFFFFFFu);
}

__device__ __forceinline__ unsigned long long warp_max_u64(unsigned long long v) {
    #pragma unroll
    for (int o = 16; o; o >>= 1) {
        unsigned long long u = __shfl_xor_sync(0xFFFFFFFFu, v, o);
        if (u > v) v = u;
    }
    return v;
}

__device__ __forceinline__ unsigned long long block_max_u64(unsigned long long v,
                                                            unsigned long long* sh) {
    v = warp_max_u64(v);
    int warp = threadIdx.x >> 5, lane = threadIdx.x & 31;
    if (lane == 0) sh[warp] = v;
    __syncthreads();
    if (warp == 0) {
        int nw = (blockDim.x + 31) >> 5;
        v = (lane < nw) ? sh[lane] : 0ULL;
        #pragma unroll
        for (int o = 4; o; o >>= 1) {
            unsigned long long u = __shfl_xor_sync(0xFFFFFFFFu, v, o);
            if (u > v) v = u;
        }
        if (lane == 0) sh[0] = v;
    }
    __syncthreads();
    unsigned long long r = sh[0];
    __syncthreads();
    return r;
}

// ---------- Kernel 1: streaming dot+sumsq (2 rows/warp/iter) + per-block top-11 ----------
__global__ void __launch_bounds__(256) score_topk_kernel(
        const float* __restrict__ coll, const float* __restrict__ emb, int n) {
    __shared__ float4 sq[D / 4];
    __shared__ unsigned long long skeys[RPB];
    __shared__ unsigned long long sh[33];

    int t = threadIdx.x;
    if (t < D / 4) sq[t] = reinterpret_cast<const float4*>(emb)[t];
    skeys[t] = 0ULL;
    __syncthreads();

    int warp = t >> 5, lane = t & 31;
    int rbeg = blockIdx.x * RPB;
    int rend = min(rbeg + RPB, n);

    #pragma unroll 1
    for (int it = 0; it < RPB / 16; it++) {
        int local = it * 16 + warp * 2;
        int row0 = rbeg + local;
        int row1 = row0 + 1;
        bool ok0 = row0 < rend, ok1 = row1 < rend;
        int r0c = min(row0, n - 1), r1c = min(row1, n - 1);   // clamp: safe loads
        const float4* rp0 = reinterpret_cast<const float4*>(coll + (size_t)r0c * D);
        const float4* rp1 = reinterpret_cast<const float4*>(coll + (size_t)r1c * D);

        float d0 = 0.f, s0 = 0.f, d1 = 0.f, s1 = 0.f;
        #pragma unroll
        for (int j = 0; j < 4; j++) {
            float4 a = __ldcs(rp0 + lane + 32 * j);
            float4 b = __ldcs(rp1 + lane + 32 * j);
            float4 q = sq[lane + 32 * j];
            d0 += a.x * q.x + a.y * q.y + a.z * q.z + a.w * q.w;
            s0 += a.x * a.x + a.y * a.y + a.z * a.z + a.w * a.w;
            d1 += b.x * q.x + b.y * q.y + b.z * q.z + b.w * q.w;
            s1 += b.x * b.x + b.y * b.y + b.z * b.z + b.w * b.w;
        }
        #pragma unroll
        for (int o = 16; o; o >>= 1) {
            d0 += __shfl_xor_sync(0xFFFFFFFFu, d0, o);
            s0 += __shfl_xor_sync(0xFFFFFFFFu, s0, o);
            d1 += __shfl_xor_sync(0xFFFFFFFFu, d1, o);
            s1 += __shfl_xor_sync(0xFFFFFFFFu, s1, o);
        }
        if (lane == 0) {
            if (ok0) skeys[local]     = make_key(d0 * rsqrtf(s0 + 1e-12f), (unsigned)row0);
            if (ok1) skeys[local + 1] = make_key(d1 * rsqrtf(s1 + 1e-12f), (unsigned)row1);
        }
    }
    __syncthreads();

    // block top-11 over 256 keys (1 per thread)
    for (int r = 0; r < KTOP; r++) {
        unsigned long long v = skeys[t];
        unsigned long long w = block_max_u64(v, sh);
        if (t == 0) g_cand[blockIdx.x * KTOP + r] = w;
        if (skeys[t] == w) skeys[t] = 0ULL;      // keys unique (index embedded)
        __syncthreads();
    }
}

// ---------- Kernel 2: parallel merge, 42 blocks x 256 keys -> 462 survivors ----------
__global__ void __launch_bounds__(256) merge_kernel(int ncand) {
    __shared__ unsigned long long sh[33];
    int t = threadIdx.x;
    int i = blockIdx.x * 256 + t;
    unsigned long long key = (i < ncand) ? g_cand[i] : 0ULL;

    for (int r = 0; r < KTOP; r++) {
        unsigned long long w = block_max_u64(key, sh);
        if (t == 0) g_cand2[blockIdx.x * KTOP + r] = w;
        if (key == w) key = 0ULL;                // keys unique: one owner
    }
}

// ---------- Kernel 3: final merge of 462 keys, vote, output ----------
__global__ void __launch_bounds__(256) finalize(
        const float* __restrict__ emb, const int* __restrict__ labels,
        float* __restrict__ out, int out_size) {
    __shared__ unsigned long long sh[33];
    __shared__ unsigned long long top[KTOP];
    __shared__ float sred[8];

    int t = threadIdx.x;
    unsigned long long k0 = (t < NC2) ? g_cand2[t] : 0ULL;
    unsigned long long k1 = (t + 256 < NC2) ? g_cand2[t + 256] : 0ULL;

    for (int r = 0; r < KTOP; r++) {
        unsigned long long m = k0 > k1 ? k0 : k1;
        unsigned long long w = block_max_u64(m, sh);
        if (t == 0) top[r] = w;
        if (k0 == w) k0 = 0ULL;
        if (k1 == w) k1 = 0ULL;
    }

    // ||q||^2
    float q0 = emb[t], q1 = emb[t + 256];
    float s = q0 * q0 + q1 * q1;
    #pragma unroll
    for (int o = 16; o; o >>= 1) s += __shfl_xor_sync(0xFFFFFFFFu, s, o);
    if ((t & 31) == 0) sred[t >> 5] = s;
    __syncthreads();

    if (t == 0) {
        float qq = 0.f;
        #pragma unroll
        for (int w = 0; w < 8; w++) qq += sred[w];
        float inv_q = 1.0f / sqrtf(qq + 1e-12f);

        float vals[KTOP]; int idxs[KTOP];
        #pragma unroll
        for (int i = 0; i < KTOP; i++) {
            vals[i] = key_val(top[i]) * inv_q;
            idxs[i] = (int)key_idx(top[i]);
        }
        int preds[KNEI];
        #pragma unroll
        for (int j = 0; j < KNEI; j++) preds[j] = labels[idxs[1 + j]];

        int counts[NCLS];
        #pragma unroll
        for (int c = 0; c < NCLS; c++) counts[c] = 0;
        #pragma unroll
        for (int j = 0; j < KNEI; j++) {
            int p = preds[j];
            if (p >= 0 && p < NCLS) counts[p]++;
        }
        int best = 0;
        for (int c = 1; c < NCLS; c++)
            if (counts[c] > counts[best]) best = c;   // first-occurrence argmax
        int pos = 0;
        for (int j = KNEI - 1; j >= 0; j--)
            if (preds[j] == best) pos = j;            // first match
        float conf = vals[1 + pos];

        int m = out_size < KTOP ? out_size : KTOP;
        for (int i = 0; i < m; i++) out[i] = vals[i];
        if (out_size > KTOP)     out[KTOP]     = (float)best;
        if (out_size > KTOP + 1) out[KTOP + 1] = conf;
        for (int i = KTOP + 2; i < out_size; i++) out[i] = 0.0f;
    }
}

extern "C" void kernel_launch(void* const* d_in, const int* in_sizes, int n_in,
                              void* d_out, int out_size) {
    const float* emb    = (const float*)d_in[0];
    const float* coll   = (const float*)d_in[1];
    const int*   labels = (const int*)d_in[2];   // jnp.int64 canonicalizes to int32 (no x64)
    int n = in_sizes[1] / D;   // 250000
    int grid = (n + RPB - 1) / RPB;              // 977

    score_topk_kernel<<<grid, 256>>>(coll, emb, n);
    merge_kernel<<<MBLK, 256>>>(grid * KTOP);
    finalize<<<1, 256>>>(emb, labels, (float*)d_out, out_size);
}

// round 7
// speedup vs baseline: 1.3095x; 1.3095x over previous
#include <cuda_runtime.h>
#include <cuda_bf16.h>
#include <math.h>

#define D     512
#define KTOP  11          // 1 + K
#define KNEI  9           // reference uses idx[1:K] = 9 neighbors
#define NCLS  100
#define RPB   256         // rows per block in fused kernel (977 blocks)
#define NMAX  250000
#define GMAX  ((NMAX + RPB - 1) / RPB)        // 977
#define NCAND (GMAX * KTOP)                   // 10747
#define MBLK  ((NCAND + 255) / 256)           // 42 merge blocks
#define NC2   (MBLK * KTOP)                   // 462

// Scratch (allocation-free rule: __device__ globals)
__device__ unsigned long long g_cand[NCAND];
__device__ unsigned long long g_cand2[NC2];

// ---- monotonic float key: bigger key == bigger value; tie -> smaller index wins ----
__device__ __forceinline__ unsigned long long make_key(float v, unsigned int idx) {
    unsigned int b = __float_as_uint(v);
    b = (b & 0x80000000u) ? ~b : (b | 0x80000000u);
    return ((unsigned long long)b << 32) | (unsigned int)(~idx);
}
__device__ __forceinline__ float key_val(unsigned long long k) {
    unsigned int o = (unsigned int)(k >> 32);
    unsigned int b = (o & 0x80000000u) ? (o ^ 0x80000000u) : ~o;
    return __uint_as_float(b);
}
__device__ __forceinline__ unsigned int key_idx(unsigned long long k) {
    return ~(unsigned int)(k & 0xFFFFFFFFu);
}

__device__ __forceinline__ unsigned long long warp_max_u64(unsigned long long v) {
    #pragma unroll
    for (int o = 16; o; o >>= 1) {
        unsigned long long u = __shfl_xor_sync(0xFFFFFFFFu, v, o);
        if (u > v) v = u;
    }
    return v;
}

__device__ __forceinline__ unsigned long long block_max_u64(unsigned long long v,
                                                            unsigned long long* sh) {
    v = warp_max_u64(v);
    int warp = threadIdx.x >> 5, lane = threadIdx.x & 31;
    if (lane == 0) sh[warp] = v;
    __syncthreads();
    if (warp == 0) {
        int nw = (blockDim.x + 31) >> 5;
        v = (lane < nw) ? sh[lane] : 0ULL;
        #pragma unroll
        for (int o = 4; o; o >>= 1) {
            unsigned long long u = __shfl_xor_sync(0xFFFFFFFFu, v, o);
            if (u > v) v = u;
        }
        if (lane == 0) sh[0] = v;
    }
    __syncthreads();
    unsigned long long r = sh[0];
    __syncthreads();
    return r;
}

// ---------- Kernel 1: streaming dot+sumsq (1 row/warp/iter) + per-block top-11 ----------
__global__ void __launch_bounds__(256, 8) score_topk_kernel(
        const float* __restrict__ coll, const float* __restrict__ emb, int n) {
    __shared__ float4 sq[D / 4];
    __shared__ unsigned long long skeys[RPB];
    __shared__ unsigned long long sh[33];

    int t = threadIdx.x;
    if (t < D / 4) sq[t] = reinterpret_cast<const float4*>(emb)[t];
    skeys[t] = 0ULL;
    __syncthreads();

    int warp = t >> 5, lane = t & 31;
    int rbeg = blockIdx.x * RPB;
    int rend = min(rbeg + RPB, n);

    for (int it = 0; it < RPB / 8; it++) {
        int local = it * 8 + warp;
        int row = rbeg + local;
        if (row >= rend) break;
        const float4* rp = reinterpret_cast<const float4*>(coll + (size_t)row * D);
        float dot = 0.f, rr = 0.f;
        #pragma unroll
        for (int j = 0; j < 4; j++) {
            float4 v = __ldcs(rp + lane + 32 * j);   // streaming: no reuse, evict-first
            float4 q = sq[lane + 32 * j];
            dot += v.x * q.x + v.y * q.y + v.z * q.z + v.w * q.w;
            rr  += v.x * v.x + v.y * v.y + v.z * v.z + v.w * v.w;
        }
        #pragma unroll
        for (int o = 16; o; o >>= 1) {
            dot += __shfl_xor_sync(0xFFFFFFFFu, dot, o);
            rr  += __shfl_xor_sync(0xFFFFFFFFu, rr, o);
        }
        if (lane == 0)
            skeys[local] = make_key(dot * rsqrtf(rr + 1e-12f), (unsigned)row);
    }
    __syncthreads();

    // block top-11 over 256 keys (1 per thread)
    for (int r = 0; r < KTOP; r++) {
        unsigned long long v = skeys[t];
        unsigned long long w = block_max_u64(v, sh);
        if (t == 0) g_cand[blockIdx.x * KTOP + r] = w;
        if (skeys[t] == w) skeys[t] = 0ULL;      // keys unique (index embedded)
        __syncthreads();
    }
}

// ---------- Kernel 2: parallel merge, 42 blocks x 256 keys -> 462 survivors ----------
__global__ void __launch_bounds__(256) merge_kernel(int ncand) {
    __shared__ unsigned long long sh[33];
    int t = threadIdx.x;
    int i = blockIdx.x * 256 + t;
    unsigned long long key = (i < ncand) ? g_cand[i] : 0ULL;

    for (int r = 0; r < KTOP; r++) {
        unsigned long long w = block_max_u64(key, sh);
        if (t == 0) g_cand2[blockIdx.x * KTOP + r] = w;
        if (key == w) key = 0ULL;                // keys unique: one owner
    }
}

// ---------- Kernel 3: final merge of 462 keys, vote, output ----------
__global__ void __launch_bounds__(256) finalize(
        const float* __restrict__ emb, const int* __restrict__ labels,
        float* __restrict__ out, int out_size) {
    __shared__ unsigned long long sh[33];
    __shared__ unsigned long long top[KTOP];
    __shared__ float sred[8];

    int t = threadIdx.x;
    unsigned long long k0 = (t < NC2) ? g_cand2[t] : 0ULL;
    unsigned long long k1 = (t + 256 < NC2) ? g_cand2[t + 256] : 0ULL;

    for (int r = 0; r < KTOP; r++) {
        unsigned long long m = k0 > k1 ? k0 : k1;
        unsigned long long w = block_max_u64(m, sh);
        if (t == 0) top[r] = w;
        if (k0 == w) k0 = 0ULL;
        if (k1 == w) k1 = 0ULL;
    }

    // ||q||^2
    float q0 = emb[t], q1 = emb[t + 256];
    float s = q0 * q0 + q1 * q1;
    #pragma unroll
    for (int o = 16; o; o >>= 1) s += __shfl_xor_sync(0xFFFFFFFFu, s, o);
    if ((t & 31) == 0) sred[t >> 5] = s;
    __syncthreads();

    if (t == 0) {
        float qq = 0.f;
        #pragma unroll
        for (int w = 0; w < 8; w++) qq += sred[w];
        float inv_q = 1.0f / sqrtf(qq + 1e-12f);

        float vals[KTOP]; int idxs[KTOP];
        #pragma unroll
        for (int i = 0; i < KTOP; i++) {
            vals[i] = key_val(top[i]) * inv_q;
            idxs[i] = (int)key_idx(top[i]);
        }
        int preds[KNEI];
        #pragma unroll
        for (int j = 0; j < KNEI; j++) preds[j] = labels[idxs[1 + j]];

        int counts[NCLS];
        #pragma unroll
        for (int c = 0; c < NCLS; c++) counts[c] = 0;
        #pragma unroll
        for (int j = 0; j < KNEI; j++) {
            int p = preds[j];
            if (p >= 0 && p < NCLS) counts[p]++;
        }
        int best = 0;
        for (int c = 1; c < NCLS; c++)
            if (counts[c] > counts[best]) best = c;   // first-occurrence argmax
        int pos = 0;
        for (int j = KNEI - 1; j >= 0; j--)
            if (preds[j] == best) pos = j;            // first match
        float conf = vals[1 + pos];

        int m = out_size < KTOP ? out_size : KTOP;
        for (int i = 0; i < m; i++) out[i] = vals[i];
        if (out_size > KTOP)     out[KTOP]     = (float)best;
        if (out_size > KTOP + 1) out[KTOP + 1] = conf;
        for (int i = KTOP + 2; i < out_size; i++) out[i] = 0.0f;
    }
}

extern "C" void kernel_launch(void* const* d_in, const int* in_sizes, int n_in,
                              void* d_out, int out_size) {
    const float* emb    = (const float*)d_in[0];
    const float* coll   = (const float*)d_in[1];
    const int*   labels = (const int*)d_in[2];   // jnp.int64 canonicalizes to int32 (no x64)
    int n = in_sizes[1] / D;   // 250000
    int grid = (n + RPB - 1) / RPB;              // 977

    score_topk_kernel<<<grid, 256>>>(coll, emb, n);
    merge_kernel<<<MBLK, 256>>>(grid * KTOP);
    finalize<<<1, 256>>>(emb, labels, (float*)d_out, out_size);
}